// round 11
// baseline (speedup 1.0000x reference)
#include <cuda_runtime.h>
#include <cuda_bf16.h>
#include <cstdint>
#include <math.h>

typedef __nv_bfloat16 bf16;

// ---------- scratch ----------
__device__ bf16 g_mag[(size_t)65536 * 576];
__device__ bf16 g_h1 [(size_t)65536 * 512];

__device__ bf16 g_Ws[256 * 320];
__device__ bf16 g_W1[576 * 512];
__device__ bf16 g_W2[512 * 128];
__device__ bf16 g_W3[128 * 128];
__device__ bf16 g_W4[128 * 128];
__device__ bf16 g_W5[128 * 384];
__device__ float g_B1[512];
__device__ float g_B2[128];
__device__ float g_B3[128];
__device__ float g_B4[128];
__device__ float g_B5[384];

// ---------- helpers ----------
__device__ __forceinline__ uint32_t smem_u32(const void* p) {
  return (uint32_t)__cvta_generic_to_shared(p);
}
__device__ __forceinline__ void cp16(uint32_t dst, const void* src) {
  asm volatile("cp.async.cg.shared.global [%0], [%1], 16;\n" :: "r"(dst), "l"(src));
}
__device__ __forceinline__ void cp_commit() { asm volatile("cp.async.commit_group;\n"); }
__device__ __forceinline__ void cp_wait0()  { asm volatile("cp.async.wait_group 0;\n"); }
__device__ __forceinline__ void cp_wait1()  { asm volatile("cp.async.wait_group 1;\n"); }
__device__ __forceinline__ void ldsm4(uint32_t* r, uint32_t a) {
  asm volatile("ldmatrix.sync.aligned.m8n8.x4.shared.b16 {%0,%1,%2,%3}, [%4];\n"
               : "=r"(r[0]), "=r"(r[1]), "=r"(r[2]), "=r"(r[3]) : "r"(a));
}
__device__ __forceinline__ void ldsm4t(uint32_t* r, uint32_t a) {
  asm volatile("ldmatrix.sync.aligned.m8n8.x4.trans.shared.b16 {%0,%1,%2,%3}, [%4];\n"
               : "=r"(r[0]), "=r"(r[1]), "=r"(r[2]), "=r"(r[3]) : "r"(a));
}
__device__ __forceinline__ void mma16816(float* d, const uint32_t* a, const uint32_t* b) {
  asm volatile(
    "mma.sync.aligned.m16n8k16.row.col.f32.bf16.bf16.f32 "
    "{%0,%1,%2,%3}, {%4,%5,%6,%7}, {%8,%9}, {%0,%1,%2,%3};\n"
    : "+f"(d[0]), "+f"(d[1]), "+f"(d[2]), "+f"(d[3])
    : "r"(a[0]), "r"(a[1]), "r"(a[2]), "r"(a[3]), "r"(b[0]), "r"(b[1]));
}
__device__ __forceinline__ float sigf(float x) { return 1.f / (1.f + expf(-x)); }

// ---------- merged weight prep ----------
__global__ void prep_all(const float* __restrict__ stw,
    const float* __restrict__ w1, const float* __restrict__ b1,
    const float* __restrict__ w2, const float* __restrict__ b2,
    const float* __restrict__ w3, const float* __restrict__ b3,
    const float* __restrict__ w4, const float* __restrict__ b4,
    const float* __restrict__ wih, const float* __restrict__ bih,
    const float* __restrict__ bhh) {
  int idx = blockIdx.x * 256 + threadIdx.x;
  if (idx < 81920) {
    int k = idx / 320, n = idx - k * 320; float v = 0.f;
    if (n < 258) { int c = n >> 1, im = n & 1; v = stw[(c + im * 129) * 256 + k]; }
    g_Ws[idx] = __float2bfloat16(v); return;
  }
  idx -= 81920;
  if (idx < 294912) {
    int kk = idx >> 9, n = idx & 511;
    int t = n >> 7, o = n & 127; float v = 0.f;
    if (kk < 516) {
      int tp = kk / 129, c = kk - tp * 129, j = tp - t + 1;
      if (j >= 0 && j < 3) v = w1[o * 387 + c * 3 + j];
    }
    g_W1[idx] = __float2bfloat16(v); return;
  }
  idx -= 294912;
  if (idx < 65536) {
    int kk = idx >> 7, n = idx & 127;
    int tout = n >> 6, o = n & 63, tin = kk >> 7, cin = kk & 127;
    int j = tin - 2 * tout + 1;
    g_W2[idx] = __float2bfloat16((j >= 0 && j < 3) ? w2[o * 384 + cin * 3 + j] : 0.f);
    return;
  }
  idx -= 65536;
  if (idx < 16384) {
    int kk = idx >> 7, n = idx & 127, tin = kk >> 6, c = kk & 63;
    g_W3[idx] = __float2bfloat16((n < 64) ? w3[n * 192 + c * 3 + tin + 1] : 0.f);
    return;
  }
  idx -= 16384;
  if (idx < 16384) {
    int kk = idx >> 7, n = idx & 127;
    g_W4[idx] = __float2bfloat16((kk < 64) ? w4[n * 192 + kk * 3 + 1] : 0.f);
    return;
  }
  idx -= 16384;
  if (idx < 49152) {
    int c = idx / 384, nn = idx - c * 384;
    int r = (nn < 128) ? nn : nn + 128;
    g_W5[idx] = __float2bfloat16(wih[r * 128 + c]); return;
  }
  idx -= 49152;
  if (idx < 512) { g_B1[idx] = b1[idx & 127]; return; }
  idx -= 512;
  if (idx < 128) { g_B2[idx] = b2[idx & 63]; return; }
  idx -= 128;
  if (idx < 128) { g_B3[idx] = (idx < 64) ? b3[idx] : 0.f; return; }
  idx -= 128;
  if (idx < 128) { g_B4[idx] = b4[idx]; return; }
  idx -= 128;
  if (idx < 384) { int r = (idx < 128) ? idx : idx + 128; g_B5[idx] = bih[r] + bhh[r]; }
}

// ---------- STFT (R8 version: B loaded once per N-subtile, minimal barriers) ----------
__global__ void __launch_bounds__(256, 2) stft_gemm(const float* __restrict__ data) {
  extern __shared__ __align__(16) char sm[];
  bf16* As = (bf16*)sm;                 // 128 x 264
  bf16* Bs = (bf16*)sm + 128 * 264;     // 256 x 72
  const int tid = threadIdx.x, lane = tid & 31, wid = tid >> 5;
  const int wm = (wid >> 1) * 32, wn = (wid & 1) * 32;
  const long cm = (long)blockIdx.x * 128;
  const long b0 = (long)blockIdx.x * 32;

  for (int it = 0; it < 64; it++) {
    int row = it * 2 + (tid >> 7);
    long b = b0 + (row >> 2);
    int t = row & 3, c = (tid & 127) * 2, j = t * 128 + c;
    float v0, v1;
    if (j >= 64 && j + 1 < 576) {
      float2 d = *(const float2*)(data + b * 512 + (j - 64));
      v0 = d.x; v1 = d.y;
    } else {
      v0 = (j < 64) ? 0.f : ((j < 576) ? data[b * 512 + j - 64] : data[b * 512 + 1086 - j]);
      int j1 = j + 1;
      v1 = (j1 < 64) ? 0.f : ((j1 < 576) ? data[b * 512 + j1 - 64] : data[b * 512 + 1086 - j1]);
    }
    __nv_bfloat162 hv; hv.x = __float2bfloat16(v0); hv.y = __float2bfloat16(v1);
    *(__nv_bfloat162*)&As[row * 264 + c] = hv;
  }

  for (int ns = 0; ns < 5; ns++) {
    const int cn = ns * 64;
    float acc[2][4][4];
    #pragma unroll
    for (int i = 0; i < 2; i++)
      #pragma unroll
      for (int j = 0; j < 4; j++)
        #pragma unroll
        for (int k = 0; k < 4; k++) acc[i][j][k] = 0.f;

    __syncthreads();
    #pragma unroll
    for (int i = 0; i < 8; i++) {
      int o = tid + i * 256;
      int r = o >> 3, c8 = (o & 7) * 8;
      cp16(smem_u32(&Bs[r * 72 + c8]), g_Ws + r * 320 + cn + c8);
    }
    cp_commit(); cp_wait0();
    __syncthreads();

    #pragma unroll
    for (int kt = 0; kt < 8; kt++) {
      #pragma unroll
      for (int ks = 0; ks < 2; ks++) {
        uint32_t a[2][4], bb[2][4];
        #pragma unroll
        for (int mt = 0; mt < 2; mt++)
          ldsm4(a[mt], smem_u32(&As[(wm + mt * 16 + (lane & 15)) * 264 +
                                    kt * 32 + ks * 16 + (lane >> 4) * 8]));
        #pragma unroll
        for (int q = 0; q < 2; q++) {
          int sel = lane >> 3;
          int krow = kt * 32 + ks * 16 + (sel & 1) * 8 + (lane & 7);
          int ncol = wn + q * 16 + (sel >> 1) * 8;
          ldsm4t(bb[q], smem_u32(&Bs[krow * 72 + ncol]));
        }
        #pragma unroll
        for (int mt = 0; mt < 2; mt++)
          #pragma unroll
          for (int nt = 0; nt < 4; nt++)
            mma16816(acc[mt][nt], a[mt], &bb[nt >> 1][(nt & 1) * 2]);
      }
    }
    #pragma unroll
    for (int mt = 0; mt < 2; mt++) {
      int r0 = wm + mt * 16 + (lane >> 2);
      #pragma unroll
      for (int nt = 0; nt < 4; nt++) {
        int col = cn + wn + nt * 8 + (lane & 3) * 2;
        if (col < 258) {
          #pragma unroll
          for (int h = 0; h < 2; h++) {
            long row = cm + r0 + h * 8;
            float v0 = acc[mt][nt][h * 2 + 0], v1 = acc[mt][nt][h * 2 + 1];
            long b = row >> 2; int t = (int)(row & 3); int ch = col >> 1;
            g_mag[b * 576 + t * 129 + ch] = __float2bfloat16(sqrtf(v0 * v0 + v1 * v1));
          }
        }
      }
    }
  }
}

// ---------- e1 GEMM: 128x128 tile, BK=64 double-buffered (bias+relu -> bf16) ----------
__global__ void __launch_bounds__(256, 2) gemm_e1(
    const bf16* __restrict__ A, const bf16* __restrict__ B,
    bf16* __restrict__ C, const float* __restrict__ bias) {
  constexpr int K = 576, NTOT = 512, NC = K / 64;
  extern __shared__ __align__(16) char sm[];
  bf16* As = (bf16*)sm;
  bf16* Bs = (bf16*)sm + 2 * 128 * 72;
  const int tid = threadIdx.x, lane = tid & 31, wid = tid >> 5;
  const int wm = (wid >> 1) * 32, wn = (wid & 1) * 64;
  const long cm = (long)blockIdx.x * 128;
  const int cn = blockIdx.y * 128;

  float acc[2][8][4];
  #pragma unroll
  for (int i = 0; i < 2; i++)
    #pragma unroll
    for (int j = 0; j < 8; j++)
      #pragma unroll
      for (int k = 0; k < 4; k++) acc[i][j][k] = 0.f;

  auto load = [&](int buf, int kc) {
    bf16* Ad = As + buf * 128 * 72;
    #pragma unroll
    for (int i = 0; i < 4; i++) {
      int o = tid + i * 256;
      int r = o >> 3, c8 = (o & 7) * 8;
      cp16(smem_u32(&Ad[r * 72 + c8]), A + (cm + r) * (long)K + kc * 64 + c8);
    }
    bf16* Bd = Bs + buf * 64 * 136;
    #pragma unroll
    for (int i = 0; i < 4; i++) {
      int o = tid + i * 256;
      int r = o >> 4, c8 = (o & 15) * 8;
      cp16(smem_u32(&Bd[r * 136 + c8]), B + (long)(kc * 64 + r) * NTOT + cn + c8);
    }
  };

  load(0, 0); cp_commit();
  for (int kc = 0; kc < NC; kc++) {
    int buf = kc & 1;
    if (kc + 1 < NC) { load(buf ^ 1, kc + 1); cp_commit(); cp_wait1(); }
    else cp_wait0();
    __syncthreads();
    bf16* Ab = As + buf * 128 * 72;
    bf16* Bb = Bs + buf * 64 * 136;
    #pragma unroll
    for (int ks = 0; ks < 4; ks++) {
      uint32_t a[2][4], bb[4][4];
      #pragma unroll
      for (int mt = 0; mt < 2; mt++)
        ldsm4(a[mt], smem_u32(&Ab[(wm + mt * 16 + (lane & 15)) * 72 +
                                  ks * 16 + (lane >> 4) * 8]));
      #pragma unroll
      for (int q = 0; q < 4; q++) {
        int sel = lane >> 3;
        int krow = ks * 16 + (sel & 1) * 8 + (lane & 7);
        int ncol = wn + q * 16 + (sel >> 1) * 8;
        ldsm4t(bb[q], smem_u32(&Bb[krow * 136 + ncol]));
      }
      #pragma unroll
      for (int mt = 0; mt < 2; mt++)
        #pragma unroll
        for (int nt = 0; nt < 8; nt++)
          mma16816(acc[mt][nt], a[mt], &bb[nt >> 1][(nt & 1) * 2]);
    }
    __syncthreads();
  }

  #pragma unroll
  for (int mt = 0; mt < 2; mt++) {
    int r0 = wm + mt * 16 + (lane >> 2);
    #pragma unroll
    for (int nt = 0; nt < 8; nt++) {
      int col = cn + wn + nt * 8 + (lane & 3) * 2;
      #pragma unroll
      for (int h = 0; h < 2; h++) {
        long row = cm + r0 + h * 8;
        float v0 = fmaxf(acc[mt][nt][h * 2 + 0] + bias[col], 0.f);
        float v1 = fmaxf(acc[mt][nt][h * 2 + 1] + bias[col + 1], 0.f);
        __nv_bfloat162 hv; hv.x = __float2bfloat16(v0); hv.y = __float2bfloat16(v1);
        *(__nv_bfloat162*)(C + row * (long)NTOT + col) = hv;
      }
    }
  }
}

// ---------- fused tail: h1 -> h2 -> h3 -> h4 -> gates -> LSTM -> out ----------
// smem pool offsets (bytes)
#define T_OA  0                       // 2 x 128x72x2  = 36864 (A stream bufs)
#define T_OB  36864                   // 2 x 64x136x2  = 34816 (B stream bufs)
#define T_OH2 71680                   // 2 chunks x 128x72x2 = 36864
#define T_OH3 108544                  // 36864
#define T_OH4 145408                  // 36864 (end 182272)
#define T_OC  71680                   // cbuf f32 128x132 = 67584 (overlays H2+part H3; used after H3 dead)
#define T_OR  182272                  // rowacc 128 f32 (end 182784)
#define T_SMEM 182784

__global__ void __launch_bounds__(256, 1) tail_fused(
    const bf16* __restrict__ h1,
    const float* __restrict__ decw, const float* __restrict__ decb,
    float* __restrict__ out) {
  extern __shared__ __align__(16) char sm[];
  const int tid = threadIdx.x, lane = tid & 31, wid = tid >> 5;
  const int wm = (wid >> 1) * 32, wn = (wid & 1) * 64;
  const long cm = (long)blockIdx.x * 128;

  bf16* As = (bf16*)(sm + T_OA);
  bf16* Bs = (bf16*)(sm + T_OB);
  float* cbuf = (float*)(sm + T_OC);
  float* rowacc = (float*)(sm + T_OR);

  float acc[2][8][4];
  auto zacc = [&]() {
    #pragma unroll
    for (int i = 0; i < 2; i++)
      #pragma unroll
      for (int j = 0; j < 8; j++)
        #pragma unroll
        for (int k = 0; k < 4; k++) acc[i][j][k] = 0.f;
  };
  // one 128x128x64 chunk: A smem (pitch 72), B smem (64x136)
  auto chunk_mma = [&](const bf16* Ab, const bf16* Bb) {
    #pragma unroll
    for (int ks = 0; ks < 4; ks++) {
      uint32_t a[2][4], bb[4][4];
      #pragma unroll
      for (int mt = 0; mt < 2; mt++)
        ldsm4(a[mt], smem_u32(&Ab[(wm + mt * 16 + (lane & 15)) * 72 +
                                  ks * 16 + (lane >> 4) * 8]));
      #pragma unroll
      for (int q = 0; q < 4; q++) {
        int sel = lane >> 3;
        int krow = ks * 16 + (sel & 1) * 8 + (lane & 7);
        int ncol = wn + q * 16 + (sel >> 1) * 8;
        ldsm4t(bb[q], smem_u32(&Bb[krow * 136 + ncol]));
      }
      #pragma unroll
      for (int mt = 0; mt < 2; mt++)
        #pragma unroll
        for (int nt = 0; nt < 8; nt++)
          mma16816(acc[mt][nt], a[mt], &bb[nt >> 1][(nt & 1) * 2]);
    }
  };
  // epilogue: relu(acc+bias) -> H chunks (64-col chunks, pitch 72)
  auto store_h = [&](bf16* Hb, const float* bias) {
    #pragma unroll
    for (int mt = 0; mt < 2; mt++) {
      int r0 = wm + mt * 16 + (lane >> 2);
      #pragma unroll
      for (int nt = 0; nt < 8; nt++) {
        int col = wn + nt * 8 + (lane & 3) * 2;
        #pragma unroll
        for (int h = 0; h < 2; h++) {
          int row = r0 + h * 8;
          float v0 = fmaxf(acc[mt][nt][h * 2 + 0] + bias[col], 0.f);
          float v1 = fmaxf(acc[mt][nt][h * 2 + 1] + bias[col + 1], 0.f);
          __nv_bfloat162 hv; hv.x = __float2bfloat16(v0); hv.y = __float2bfloat16(v1);
          *(__nv_bfloat162*)&Hb[(col >> 6) * 9216 + row * 72 + (col & 63)] = hv;
        }
      }
    }
  };
  // load one 64-row B chunk (N=128 cols) from K-major weights W[k][*], ld=ldw, col offset co
  auto loadB = [&](int buf, const bf16* W, int ldw, int kc, int co) {
    bf16* Bd = Bs + buf * 8704;
    #pragma unroll
    for (int i = 0; i < 4; i++) {
      int o = tid + i * 256;
      int r = o >> 4, c8 = (o & 15) * 8;
      cp16(smem_u32(&Bd[r * 136 + c8]), W + (long)(kc * 64 + r) * ldw + co + c8);
    }
  };

  // ---- stage 1: h2 = relu(h1 @ W2 + b2), K=512 streamed ----
  auto loadA1 = [&](int buf, int kc) {
    bf16* Ad = As + buf * 9216;
    #pragma unroll
    for (int i = 0; i < 4; i++) {
      int o = tid + i * 256;
      int r = o >> 3, c8 = (o & 7) * 8;
      cp16(smem_u32(&Ad[r * 72 + c8]), h1 + (cm + r) * 512L + kc * 64 + c8);
    }
  };
  zacc();
  loadA1(0, 0); loadB(0, g_W2, 128, 0, 0); cp_commit();
  for (int kc = 0; kc < 8; kc++) {
    int buf = kc & 1;
    if (kc < 7) { loadA1(buf ^ 1, kc + 1); loadB(buf ^ 1, g_W2, 128, kc + 1, 0); cp_commit(); cp_wait1(); }
    else cp_wait0();
    __syncthreads();
    chunk_mma(As + buf * 9216, Bs + buf * 8704);
    __syncthreads();
  }
  store_h((bf16*)(sm + T_OH2), g_B2);
  __syncthreads();

  // ---- stage 2: h3 = relu(h2 @ W3 + b3), K=128 (A in smem) ----
  loadB(0, g_W3, 128, 0, 0); loadB(1, g_W3, 128, 1, 0); cp_commit(); cp_wait0();
  __syncthreads();
  zacc();
  chunk_mma((bf16*)(sm + T_OH2), Bs);
  chunk_mma((bf16*)(sm + T_OH2) + 9216, Bs + 8704);
  __syncthreads();
  store_h((bf16*)(sm + T_OH3), g_B3);
  __syncthreads();

  // ---- stage 3: h4 = relu(h3 @ W4 + b4) ----
  loadB(0, g_W4, 128, 0, 0); loadB(1, g_W4, 128, 1, 0); cp_commit(); cp_wait0();
  __syncthreads();
  zacc();
  chunk_mma((bf16*)(sm + T_OH3), Bs);
  chunk_mma((bf16*)(sm + T_OH3) + 9216, Bs + 8704);
  __syncthreads();
  store_h((bf16*)(sm + T_OH4), g_B4);
  if (tid < 128) rowacc[tid] = 0.f;
  __syncthreads();

  // ---- stage 4: gates (3 passes of N=128) + fused LSTM ----
  float part[2][2];  // per (mt,h) row partial for pass 2
  #pragma unroll
  for (int i = 0; i < 2; i++) { part[i][0] = 0.f; part[i][1] = 0.f; }

  for (int p = 0; p < 3; p++) {
    loadB(0, g_W5, 384, 0, 128 * p); loadB(1, g_W5, 384, 1, 128 * p);
    cp_commit(); cp_wait0();
    __syncthreads();
    zacc();
    chunk_mma((bf16*)(sm + T_OH4), Bs);
    chunk_mma((bf16*)(sm + T_OH4) + 9216, Bs + 8704);
    #pragma unroll
    for (int mt = 0; mt < 2; mt++) {
      int r0 = wm + mt * 16 + (lane >> 2);
      #pragma unroll
      for (int nt = 0; nt < 8; nt++) {
        int col = wn + nt * 8 + (lane & 3) * 2;
        #pragma unroll
        for (int h = 0; h < 2; h++) {
          int row = r0 + h * 8;
          #pragma unroll
          for (int e = 0; e < 2; e++) {
            int j = col + e;
            float g = acc[mt][nt][h * 2 + e] + g_B5[128 * p + j];
            float* cc = &cbuf[row * 132 + j];
            if (p == 0) *cc = sigf(g);
            else if (p == 1) *cc = *cc * tanhf(g);
            else {
              float y = fmaxf(sigf(g) * tanhf(*cc), 0.f);
              part[mt][h] += decw[j] * y;
            }
          }
        }
      }
    }
    __syncthreads();
  }
  #pragma unroll
  for (int mt = 0; mt < 2; mt++)
    #pragma unroll
    for (int h = 0; h < 2; h++)
      atomicAdd(&rowacc[wm + mt * 16 + (lane >> 2) + h * 8], part[mt][h]);
  __syncthreads();
  if (tid < 128) out[cm + tid] = sigf(rowacc[tid] + decb[0]);
}

extern "C" void kernel_launch(void* const* d_in, const int* in_sizes, int n_in,
                              void* d_out, int out_size) {
  const float* data = (const float*)d_in[0];
  const float* stw  = (const float*)d_in[2];
  const float* e1w  = (const float*)d_in[3];
  const float* e1b  = (const float*)d_in[4];
  const float* e2w  = (const float*)d_in[5];
  const float* e2b  = (const float*)d_in[6];
  const float* e3w  = (const float*)d_in[7];
  const float* e3b  = (const float*)d_in[8];
  const float* e4w  = (const float*)d_in[9];
  const float* e4b  = (const float*)d_in[10];
  const float* wih  = (const float*)d_in[11];
  const float* bih  = (const float*)d_in[13];
  const float* bhh  = (const float*)d_in[14];
  const float* decw = (const float*)d_in[15];
  const float* decb = (const float*)d_in[16];
  float* out = (float*)d_out;

  void *pmag, *ph1, *pW1, *pB1;
  cudaGetSymbolAddress(&pmag, g_mag);
  cudaGetSymbolAddress(&ph1, g_h1);
  cudaGetSymbolAddress(&pW1, g_W1);
  cudaGetSymbolAddress(&pB1, g_B1);

  const int STFT_SMEM = (128 * 264 + 256 * 72) * 2;
  const int G3_SMEM   = (2 * 128 * 72 + 2 * 64 * 136) * 2;
  cudaFuncSetAttribute(stft_gemm, cudaFuncAttributeMaxDynamicSharedMemorySize, STFT_SMEM);
  cudaFuncSetAttribute(gemm_e1, cudaFuncAttributeMaxDynamicSharedMemorySize, G3_SMEM);
  cudaFuncSetAttribute(tail_fused, cudaFuncAttributeMaxDynamicSharedMemorySize, T_SMEM);

  prep_all<<<2054, 256>>>(stw, e1w, e1b, e2w, e2b, e3w, e3b, e4w, e4b, wih, bih, bhh);
  stft_gemm<<<2048, 256, STFT_SMEM>>>(data);
  gemm_e1<<<dim3(512, 4), 256, G3_SMEM>>>((const bf16*)pmag, (const bf16*)pW1,
                                          (bf16*)ph1, (const float*)pB1);
  tail_fused<<<512, 256, T_SMEM>>>((const bf16*)ph1, decw, decb, out);
}